// round 5
// baseline (speedup 1.0000x reference)
#include <cuda_runtime.h>
#include <cuda_bf16.h>
#include <cstdint>

#define NTOK   (8 * 2048)
#define EDIM   512
#define NHEAD  64
#define DK     8

typedef unsigned long long u64;

// Split-bf16 operands (hi + lo together carry ~17 mantissa bits of fp32)
__device__ __nv_bfloat16 g_Zh[NTOK * EDIM];
__device__ __nv_bfloat16 g_Zl[NTOK * EDIM];
__device__ __nv_bfloat16 g_Wh[EDIM * EDIM];
__device__ __nv_bfloat16 g_Wl[EDIM * EDIM];

__device__ __forceinline__ uint32_t smem_to_u32(const void* p) {
    uint32_t a;
    asm("{ .reg .u64 t; cvta.to.shared.u64 t, %1; cvt.u32.u64 %0, t; }" : "=r"(a) : "l"(p));
    return a;
}

// Packed fp32x2 math (Blackwell)
__device__ __forceinline__ void fma2(u64 &d, u64 a, u64 b) {
    asm("fma.rn.f32x2 %0, %1, %2, %3;" : "=l"(d) : "l"(a), "l"(b), "l"(d));
}
__device__ __forceinline__ void add2(u64 &d, u64 a) {
    asm("add.rn.f32x2 %0, %1, %2;" : "=l"(d) : "l"(d), "l"(a));
}
__device__ __forceinline__ u64 pack2(float lo, float hi) {
    u64 r; asm("mov.b64 %0, {%1, %2};" : "=l"(r) : "f"(lo), "f"(hi)); return r;
}
__device__ __forceinline__ float2 unpack2(u64 v) {
    float2 r; asm("mov.b64 {%0, %1}, %2;" : "=f"(r.x), "=f"(r.y) : "l"(v)); return r;
}
__device__ __forceinline__ float ex2(float x) {
    float r; asm("ex2.approx.ftz.f32 %0, %1;" : "=f"(r) : "f"(x)); return r;
}

// Baseline-PTX tensor path (sm_80+)
#define CP16(dst, src) \
    asm volatile("cp.async.cg.shared.global [%0], [%1], 16;" :: "r"(dst), "l"(src))
#define CP_COMMIT()  asm volatile("cp.async.commit_group;" ::: "memory")
#define CP_WAIT1()   asm volatile("cp.async.wait_group 1;" ::: "memory")
#define CP_WAIT0()   asm volatile("cp.async.wait_group 0;" ::: "memory")

#define LDSM4(r, addr) \
    asm volatile("ldmatrix.sync.aligned.m8n8.x4.shared.b16 {%0,%1,%2,%3}, [%4];" \
        : "=r"((r)[0]), "=r"((r)[1]), "=r"((r)[2]), "=r"((r)[3]) : "r"(addr))

#define MMA_BF16(d, a, b) \
    asm volatile("mma.sync.aligned.m16n8k16.row.col.f32.bf16.bf16.f32 " \
        "{%0,%1,%2,%3}, {%4,%5,%6,%7}, {%8,%9}, {%0,%1,%2,%3};" \
        : "+f"((d)[0]), "+f"((d)[1]), "+f"((d)[2]), "+f"((d)[3]) \
        : "r"((a)[0]), "r"((a)[1]), "r"((a)[2]), "r"((a)[3]), "r"((b)[0]), "r"((b)[1]))

// ---------------------------------------------------------------------------
// Kernel A: blocks [0, QBLOCKS): projection + head-axis attention (warp/token)
//           blocks [QBLOCKS, ...): W hi/lo split (merged launch)
// ---------------------------------------------------------------------------
#define QBLOCKS (NTOK / 8)

__global__ __launch_bounds__(256) void qattn_kernel(const float* __restrict__ x,
                                                    const float* __restrict__ theta,
                                                    const float* __restrict__ W) {
    const int tid = threadIdx.x;

    if (blockIdx.x >= QBLOCKS) {   // -------- W split branch --------
        int i = (blockIdx.x - QBLOCKS) * 256 + tid;
        float w = W[i];
        __nv_bfloat16 h = __float2bfloat16(w);
        g_Wh[i] = h;
        g_Wl[i] = __float2bfloat16(w - __bfloat162float(h));
        return;
    }

    __shared__ float Psm[8][NHEAD][DK];
    __shared__ float th[DK];
    if (tid < DK) th[tid] = theta[tid];
    __syncthreads();

    const int w = tid >> 5, lane = tid & 31;
    const int token = blockIdx.x * 8 + w;
    const float* xr = x + (size_t)token * EDIM;

    float pa[8], pb[8];
    {
        float4 v0 = *(const float4*)(xr + lane * 8);
        float4 v1 = *(const float4*)(xr + lane * 8 + 4);
        pa[0] = __cosf(v0.x + th[0]); pa[1] = __cosf(v0.y + th[1]);
        pa[2] = __cosf(v0.z + th[2]); pa[3] = __cosf(v0.w + th[3]);
        pa[4] = __cosf(v1.x + th[4]); pa[5] = __cosf(v1.y + th[5]);
        pa[6] = __cosf(v1.z + th[6]); pa[7] = __cosf(v1.w + th[7]);
        float4 u0 = *(const float4*)(xr + (lane + 32) * 8);
        float4 u1 = *(const float4*)(xr + (lane + 32) * 8 + 4);
        pb[0] = __cosf(u0.x + th[0]); pb[1] = __cosf(u0.y + th[1]);
        pb[2] = __cosf(u0.z + th[2]); pb[3] = __cosf(u0.w + th[3]);
        pb[4] = __cosf(u1.x + th[4]); pb[5] = __cosf(u1.y + th[5]);
        pb[6] = __cosf(u1.z + th[6]); pb[7] = __cosf(u1.w + th[7]);
    }

    float* Pw = &Psm[w][0][0];
    *(float4*)(Pw + lane * 8)            = make_float4(pa[0], pa[1], pa[2], pa[3]);
    *(float4*)(Pw + lane * 8 + 4)        = make_float4(pa[4], pa[5], pa[6], pa[7]);
    *(float4*)(Pw + (lane + 32) * 8)     = make_float4(pb[0], pb[1], pb[2], pb[3]);
    *(float4*)(Pw + (lane + 32) * 8 + 4) = make_float4(pb[4], pb[5], pb[6], pb[7]);
    __syncwarp();

    const float inv = 0.35355339059327373f * 1.4426950408889634f;  // /sqrt(8)/ln2
    u64 uqa[4], uqb[4];
#pragma unroll
    for (int i = 0; i < 4; i++) {
        uqa[i] = pack2(pa[2*i] * inv, pa[2*i+1] * inv);
        uqb[i] = pack2(pb[2*i] * inv, pb[2*i+1] * inv);
    }

    u64 sum2 = 0ull, uoa[4], uob[4];
#pragma unroll
    for (int i = 0; i < 4; i++) { uoa[i] = 0ull; uob[i] = 0ull; }

    const ulonglong2* Pw2 = (const ulonglong2*)Pw;
#pragma unroll 8
    for (int g = 0; g < NHEAD; g++) {
        ulonglong2 p0 = Pw2[g * 2];
        ulonglong2 p1 = Pw2[g * 2 + 1];
        u64 ta = 0ull, tb = 0ull;
        fma2(ta, uqa[0], p0.x); fma2(ta, uqa[1], p0.y);
        fma2(ta, uqa[2], p1.x); fma2(ta, uqa[3], p1.y);
        fma2(tb, uqb[0], p0.x); fma2(tb, uqb[1], p0.y);
        fma2(tb, uqb[2], p1.x); fma2(tb, uqb[3], p1.y);
        float2 va = unpack2(ta), vb = unpack2(tb);
        float wa = ex2(va.x + va.y);
        float wb = ex2(vb.x + vb.y);
        add2(sum2, pack2(wa, wb));
        u64 waa = pack2(wa, wa), wbb = pack2(wb, wb);
        fma2(uoa[0], p0.x, waa); fma2(uoa[1], p0.y, waa);
        fma2(uoa[2], p1.x, waa); fma2(uoa[3], p1.y, waa);
        fma2(uob[0], p0.x, wbb); fma2(uob[1], p0.y, wbb);
        fma2(uob[2], p1.x, wbb); fma2(uob[3], p1.y, wbb);
    }

    float2 sums = unpack2(sum2);
    const float ra = 1.0f / sums.x, rb = 1.0f / sums.y;
    const int b = token >> 11, s = token & 2047;
    const size_t idxA = ((size_t)b << 20) + ((size_t)lane << 14) + s * 8;
    const size_t idxB = ((size_t)b << 20) + ((size_t)(lane + 32) << 14) + s * 8;

    union { __nv_bfloat16 e[8]; uint4 v; } uh, ul;
#pragma unroll
    for (int i = 0; i < 4; i++) {
        float2 v = unpack2(uoa[i]);
        float z0 = v.x * ra, z1 = v.y * ra;
        uh.e[2*i]   = __float2bfloat16(z0);
        ul.e[2*i]   = __float2bfloat16(z0 - __bfloat162float(uh.e[2*i]));
        uh.e[2*i+1] = __float2bfloat16(z1);
        ul.e[2*i+1] = __float2bfloat16(z1 - __bfloat162float(uh.e[2*i+1]));
    }
    *(uint4*)(g_Zh + idxA) = uh.v;
    *(uint4*)(g_Zl + idxA) = ul.v;
#pragma unroll
    for (int i = 0; i < 4; i++) {
        float2 v = unpack2(uob[i]);
        float z0 = v.x * rb, z1 = v.y * rb;
        uh.e[2*i]   = __float2bfloat16(z0);
        ul.e[2*i]   = __float2bfloat16(z0 - __bfloat162float(uh.e[2*i]));
        uh.e[2*i+1] = __float2bfloat16(z1);
        ul.e[2*i+1] = __float2bfloat16(z1 - __bfloat162float(uh.e[2*i+1]));
    }
    *(uint4*)(g_Zh + idxB) = uh.v;
    *(uint4*)(g_Zl + idxB) = ul.v;
}

// ---------------------------------------------------------------------------
// Kernel B: HMMA GEMM  Y[16384,512] = Z @ W^T + bias  (split-bf16, fp32 acc)
// CTA 128x128, 512 threads = 16 warps x (32x32 warp tile), K chunks of 32.
// SMEM: 64B rows, XOR swizzle slot = c ^ ((r>>1)&3)  -> conflict-free ldmatrix.
// Double-buffered cp.async; 2 CTAs/SM (32 warps, 50% occ).
// ---------------------------------------------------------------------------
#define OPBYTES 8192                 // 128 rows x 64 B per operand array
#define O_ZH    0
#define O_ZL    (1 * OPBYTES)
#define O_WH    (2 * OPBYTES)
#define O_WL    (3 * OPBYTES)
#define STAGE   (4 * OPBYTES)        // 32768 B
#define SMEM_TOTAL (2 * STAGE)       // 65536 B

__device__ __forceinline__ uint32_t swaddr(uint32_t base, int row, int slot) {
    return base + row * 64 + ((slot ^ ((row >> 1) & 3)) << 4);
}

__global__ __launch_bounds__(512, 2) void gemm_kernel(const float* __restrict__ bias,
                                                      float* __restrict__ Y) {
    extern __shared__ char smem[];
    const uint32_t smem_base = smem_to_u32(smem);
    const int tid = threadIdx.x, wid = tid >> 5, lane = tid & 31;
    const int bx = blockIdx.x, by = blockIdx.y;

    // cp.async slice: thread handles one 64B row-chunk of one operand array
    const int arr = tid >> 7;          // 0=Zh 1=Zl 2=Wh 3=Wl
    const int r   = tid & 127;
    const __nv_bfloat16* gsrc;
    if (arr == 0)      gsrc = g_Zh + (size_t)(by * 128 + r) * EDIM;
    else if (arr == 1) gsrc = g_Zl + (size_t)(by * 128 + r) * EDIM;
    else if (arr == 2) gsrc = g_Wh + (size_t)(bx * 128 + r) * EDIM;
    else               gsrc = g_Wl + (size_t)(bx * 128 + r) * EDIM;
    uint32_t sdst[4];
#pragma unroll
    for (int s = 0; s < 4; s++) sdst[s] = swaddr(smem_base + arr * OPBYTES, r, s);

    // warp tile: wm in {0..3} (32 rows), wn in {0..3} (32 cols)
    const int wm = wid & 3, wn = wid >> 2;

    const int la_row = lane & 15;                       // A row in 16-tile
    const int la_kh  = (lane >> 4) & 1;                 // A 16B k-half slot
    const int lb_n   = (lane & 7) + ((lane & 16) >> 1); // B n in 16-group
    const int lb_kh  = (lane >> 3) & 1;

    float acc[2][4][4];
#pragma unroll
    for (int i = 0; i < 2; i++)
#pragma unroll
        for (int j = 0; j < 4; j++)
#pragma unroll
            for (int k = 0; k < 4; k++) acc[i][j][k] = 0.f;

#define ISSUE(c, st) do { \
    const char* s0 = (const char*)(gsrc + (size_t)(c) * 32); \
    uint32_t stb = (st) * STAGE; \
    CP16(sdst[0] + stb, s0); \
    CP16(sdst[1] + stb, s0 + 16); \
    CP16(sdst[2] + stb, s0 + 32); \
    CP16(sdst[3] + stb, s0 + 48); \
} while (0)

    ISSUE(0, 0);
    CP_COMMIT();

    for (int c = 0; c < EDIM / 32; c++) {
        const int st = c & 1;
        if (c + 1 < EDIM / 32) { ISSUE(c + 1, st ^ 1); CP_COMMIT(); CP_WAIT1(); }
        else                   { CP_WAIT0(); }
        __syncthreads();

        const uint32_t sg = smem_base + st * STAGE;

#pragma unroll
        for (int ks = 0; ks < 2; ks++) {
            const int slA = ks * 2 + la_kh;
            const int slB = ks * 2 + lb_kh;
            uint32_t bh[4][2], bl[4][2];
#pragma unroll
            for (int np = 0; np < 2; np++) {
                const int rn = wn * 32 + np * 16 + lb_n;
                uint32_t t[4];
                LDSM4(t, swaddr(sg + O_WH, rn, slB));
                bh[2*np][0] = t[0]; bh[2*np][1] = t[1];
                bh[2*np+1][0] = t[2]; bh[2*np+1][1] = t[3];
                LDSM4(t, swaddr(sg + O_WL, rn, slB));
                bl[2*np][0] = t[0]; bl[2*np][1] = t[1];
                bl[2*np+1][0] = t[2]; bl[2*np+1][1] = t[3];
            }
#pragma unroll
            for (int mt = 0; mt < 2; mt++) {
                const int rm = wm * 32 + mt * 16 + la_row;
                uint32_t ah[4], al[4];
                LDSM4(ah, swaddr(sg + O_ZH, rm, slA));
                LDSM4(al, swaddr(sg + O_ZL, rm, slA));
#pragma unroll
                for (int nt = 0; nt < 4; nt++) {
                    MMA_BF16(acc[mt][nt], ah, bh[nt]);
                    MMA_BF16(acc[mt][nt], al, bh[nt]);
                    MMA_BF16(acc[mt][nt], ah, bl[nt]);
                }
            }
        }
        __syncthreads();
    }

    // Epilogue
    const int g = lane >> 2, cq = 2 * (lane & 3);
#pragma unroll
    for (int nt = 0; nt < 4; nt++) {
        const int col = bx * 128 + wn * 32 + nt * 8 + cq;
        const float2 bv = *(const float2*)(bias + col);
#pragma unroll
        for (int mt = 0; mt < 2; mt++) {
            const int r0 = by * 128 + wm * 32 + mt * 16 + g;
            float2 v0 = make_float2(acc[mt][nt][0] + bv.x, acc[mt][nt][1] + bv.y);
            float2 v1 = make_float2(acc[mt][nt][2] + bv.x, acc[mt][nt][3] + bv.y);
            *(float2*)(Y + (size_t)r0 * EDIM + col)       = v0;
            *(float2*)(Y + (size_t)(r0 + 8) * EDIM + col) = v1;
        }
    }
}

// ---------------------------------------------------------------------------
extern "C" void kernel_launch(void* const* d_in, const int* in_sizes, int n_in,
                              void* d_out, int out_size) {
    const float* x     = (const float*)d_in[0];
    const float* theta = (const float*)d_in[1];
    const float* W     = (const float*)d_in[2];
    const float* bias  = (const float*)d_in[3];
    float* out = (float*)d_out;

    cudaFuncSetAttribute(gemm_kernel, cudaFuncAttributeMaxDynamicSharedMemorySize, SMEM_TOTAL);

    qattn_kernel<<<QBLOCKS + EDIM * EDIM / 256, 256>>>(x, theta, W);
    gemm_kernel<<<dim3(EDIM / 128, NTOK / 128), 512, SMEM_TOTAL>>>(bias, out);
}

// round 6
// speedup vs baseline: 1.1656x; 1.1656x over previous
#include <cuda_runtime.h>
#include <cuda_bf16.h>
#include <cstdint>

#define NTOK   (8 * 2048)
#define EDIM   512
#define NHEAD  64
#define DK     8

typedef unsigned long long u64;

// Split-bf16 operands (hi + lo together carry ~17 mantissa bits of fp32)
__device__ __nv_bfloat16 g_Zh[NTOK * EDIM];
__device__ __nv_bfloat16 g_Zl[NTOK * EDIM];
__device__ __nv_bfloat16 g_Wh[EDIM * EDIM];
__device__ __nv_bfloat16 g_Wl[EDIM * EDIM];

__device__ __forceinline__ uint32_t smem_to_u32(const void* p) {
    uint32_t a;
    asm("{ .reg .u64 t; cvta.to.shared.u64 t, %1; cvt.u32.u64 %0, t; }" : "=r"(a) : "l"(p));
    return a;
}

// Packed fp32x2 math (Blackwell)
__device__ __forceinline__ void fma2(u64 &d, u64 a, u64 b) {
    asm("fma.rn.f32x2 %0, %1, %2, %3;" : "=l"(d) : "l"(a), "l"(b), "l"(d));
}
__device__ __forceinline__ void add2(u64 &d, u64 a) {
    asm("add.rn.f32x2 %0, %1, %2;" : "=l"(d) : "l"(d), "l"(a));
}
__device__ __forceinline__ u64 pack2(float lo, float hi) {
    u64 r; asm("mov.b64 %0, {%1, %2};" : "=l"(r) : "f"(lo), "f"(hi)); return r;
}
__device__ __forceinline__ float2 unpack2(u64 v) {
    float2 r; asm("mov.b64 {%0, %1}, %2;" : "=f"(r.x), "=f"(r.y) : "l"(v)); return r;
}
__device__ __forceinline__ float ex2(float x) {
    float r; asm("ex2.approx.ftz.f32 %0, %1;" : "=f"(r) : "f"(x)); return r;
}

// Baseline-PTX tensor path (sm_80+)
#define CP16(dst, src) \
    asm volatile("cp.async.cg.shared.global [%0], [%1], 16;" :: "r"(dst), "l"(src))
#define CP_COMMIT()  asm volatile("cp.async.commit_group;" ::: "memory")
#define CP_WAIT1()   asm volatile("cp.async.wait_group 1;" ::: "memory")
#define CP_WAIT0()   asm volatile("cp.async.wait_group 0;" ::: "memory")

#define LDSM4(r, addr) \
    asm volatile("ldmatrix.sync.aligned.m8n8.x4.shared.b16 {%0,%1,%2,%3}, [%4];" \
        : "=r"((r)[0]), "=r"((r)[1]), "=r"((r)[2]), "=r"((r)[3]) : "r"(addr))

#define MMA_BF16(d, a, b) \
    asm volatile("mma.sync.aligned.m16n8k16.row.col.f32.bf16.bf16.f32 " \
        "{%0,%1,%2,%3}, {%4,%5,%6,%7}, {%8,%9}, {%0,%1,%2,%3};" \
        : "+f"((d)[0]), "+f"((d)[1]), "+f"((d)[2]), "+f"((d)[3]) \
        : "r"((a)[0]), "r"((a)[1]), "r"((a)[2]), "r"((a)[3]), "r"((b)[0]), "r"((b)[1]))

// ---------------------------------------------------------------------------
// Kernel A: blocks [0, QBLOCKS): projection + head-axis attention (warp/token)
//           blocks [QBLOCKS, ...): W hi/lo split (merged launch)
// ---------------------------------------------------------------------------
#define QBLOCKS (NTOK / 8)

__global__ __launch_bounds__(256) void qattn_kernel(const float* __restrict__ x,
                                                    const float* __restrict__ theta,
                                                    const float* __restrict__ W) {
    const int tid = threadIdx.x;

    if (blockIdx.x >= QBLOCKS) {   // -------- W split branch --------
        int i = (blockIdx.x - QBLOCKS) * 256 + tid;
        float w = W[i];
        __nv_bfloat16 h = __float2bfloat16(w);
        g_Wh[i] = h;
        g_Wl[i] = __float2bfloat16(w - __bfloat162float(h));
        return;
    }

    __shared__ float Psm[8][NHEAD][DK];
    __shared__ float th[DK];
    if (tid < DK) th[tid] = theta[tid];
    __syncthreads();

    const int w = tid >> 5, lane = tid & 31;
    const int token = blockIdx.x * 8 + w;
    const float* xr = x + (size_t)token * EDIM;

    float pa[8], pb[8];
    {
        float4 v0 = *(const float4*)(xr + lane * 8);
        float4 v1 = *(const float4*)(xr + lane * 8 + 4);
        pa[0] = __cosf(v0.x + th[0]); pa[1] = __cosf(v0.y + th[1]);
        pa[2] = __cosf(v0.z + th[2]); pa[3] = __cosf(v0.w + th[3]);
        pa[4] = __cosf(v1.x + th[4]); pa[5] = __cosf(v1.y + th[5]);
        pa[6] = __cosf(v1.z + th[6]); pa[7] = __cosf(v1.w + th[7]);
        float4 u0 = *(const float4*)(xr + (lane + 32) * 8);
        float4 u1 = *(const float4*)(xr + (lane + 32) * 8 + 4);
        pb[0] = __cosf(u0.x + th[0]); pb[1] = __cosf(u0.y + th[1]);
        pb[2] = __cosf(u0.z + th[2]); pb[3] = __cosf(u0.w + th[3]);
        pb[4] = __cosf(u1.x + th[4]); pb[5] = __cosf(u1.y + th[5]);
        pb[6] = __cosf(u1.z + th[6]); pb[7] = __cosf(u1.w + th[7]);
    }

    float* Pw = &Psm[w][0][0];
    *(float4*)(Pw + lane * 8)            = make_float4(pa[0], pa[1], pa[2], pa[3]);
    *(float4*)(Pw + lane * 8 + 4)        = make_float4(pa[4], pa[5], pa[6], pa[7]);
    *(float4*)(Pw + (lane + 32) * 8)     = make_float4(pb[0], pb[1], pb[2], pb[3]);
    *(float4*)(Pw + (lane + 32) * 8 + 4) = make_float4(pb[4], pb[5], pb[6], pb[7]);
    __syncwarp();

    const float inv = 0.35355339059327373f * 1.4426950408889634f;  // /sqrt(8)/ln2
    u64 uqa[4], uqb[4];
#pragma unroll
    for (int i = 0; i < 4; i++) {
        uqa[i] = pack2(pa[2*i] * inv, pa[2*i+1] * inv);
        uqb[i] = pack2(pb[2*i] * inv, pb[2*i+1] * inv);
    }

    u64 sum2 = 0ull, uoa[4], uob[4];
#pragma unroll
    for (int i = 0; i < 4; i++) { uoa[i] = 0ull; uob[i] = 0ull; }

    const ulonglong2* Pw2 = (const ulonglong2*)Pw;
#pragma unroll 8
    for (int g = 0; g < NHEAD; g++) {
        ulonglong2 p0 = Pw2[g * 2];
        ulonglong2 p1 = Pw2[g * 2 + 1];
        u64 ta = 0ull, tb = 0ull;
        fma2(ta, uqa[0], p0.x); fma2(ta, uqa[1], p0.y);
        fma2(ta, uqa[2], p1.x); fma2(ta, uqa[3], p1.y);
        fma2(tb, uqb[0], p0.x); fma2(tb, uqb[1], p0.y);
        fma2(tb, uqb[2], p1.x); fma2(tb, uqb[3], p1.y);
        float2 va = unpack2(ta), vb = unpack2(tb);
        float wa = ex2(va.x + va.y);
        float wb = ex2(vb.x + vb.y);
        add2(sum2, pack2(wa, wb));
        u64 waa = pack2(wa, wa), wbb = pack2(wb, wb);
        fma2(uoa[0], p0.x, waa); fma2(uoa[1], p0.y, waa);
        fma2(uoa[2], p1.x, waa); fma2(uoa[3], p1.y, waa);
        fma2(uob[0], p0.x, wbb); fma2(uob[1], p0.y, wbb);
        fma2(uob[2], p1.x, wbb); fma2(uob[3], p1.y, wbb);
    }

    float2 sums = unpack2(sum2);
    const float ra = 1.0f / sums.x, rb = 1.0f / sums.y;
    const int b = token >> 11, s = token & 2047;
    const size_t idxA = ((size_t)b << 20) + ((size_t)lane << 14) + s * 8;
    const size_t idxB = ((size_t)b << 20) + ((size_t)(lane + 32) << 14) + s * 8;

    union { __nv_bfloat16 e[8]; uint4 v; } uh, ul;
#pragma unroll
    for (int i = 0; i < 4; i++) {
        float2 v = unpack2(uoa[i]);
        float z0 = v.x * ra, z1 = v.y * ra;
        uh.e[2*i]   = __float2bfloat16(z0);
        ul.e[2*i]   = __float2bfloat16(z0 - __bfloat162float(uh.e[2*i]));
        uh.e[2*i+1] = __float2bfloat16(z1);
        ul.e[2*i+1] = __float2bfloat16(z1 - __bfloat162float(uh.e[2*i+1]));
    }
    *(uint4*)(g_Zh + idxA) = uh.v;
    *(uint4*)(g_Zl + idxA) = ul.v;
#pragma unroll
    for (int i = 0; i < 4; i++) {
        float2 v = unpack2(uob[i]);
        float z0 = v.x * rb, z1 = v.y * rb;
        uh.e[2*i]   = __float2bfloat16(z0);
        ul.e[2*i]   = __float2bfloat16(z0 - __bfloat162float(uh.e[2*i]));
        uh.e[2*i+1] = __float2bfloat16(z1);
        ul.e[2*i+1] = __float2bfloat16(z1 - __bfloat162float(uh.e[2*i+1]));
    }
    *(uint4*)(g_Zh + idxB) = uh.v;
    *(uint4*)(g_Zl + idxB) = ul.v;
}

// ---------------------------------------------------------------------------
// Kernel B: HMMA GEMM  Y[16384,512] = Z @ W^T + bias  (split-bf16, fp32 acc)
// CTA 128x128, 8 warps x (64x32), K chunks of 32, double-buffered cp.async.
// SMEM row stride 80B -> conflict-free ldmatrix.
// MMA schedule: product-major within mt-pairs -> acc reuse distance 8 MMAs
// (was 3), covering HMMA latency without more warps.
// ---------------------------------------------------------------------------
#define RSTRIDE 80
#define ARR     (128 * RSTRIDE)
#define O_ZH    0
#define O_ZL    (1 * ARR)
#define O_WH    (2 * ARR)
#define O_WL    (3 * ARR)
#define STAGE   (4 * ARR)           // 40960 B
#define SMEM_TOTAL (2 * STAGE)      // 81920 B

__global__ __launch_bounds__(256, 2) void gemm_kernel(const float* __restrict__ bias,
                                                      float* __restrict__ Y) {
    extern __shared__ char smem[];
    const uint32_t smem_base = smem_to_u32(smem);
    const int tid = threadIdx.x, wid = tid >> 5, lane = tid & 31;
    const int bx = blockIdx.x, by = blockIdx.y;

    const int row = tid >> 1, half = tid & 1;
    const size_t zbase = (size_t)(by * 128 + row) * EDIM + half * 16;
    const size_t wbase = (size_t)(bx * 128 + row) * EDIM + half * 16;
    const uint32_t sdst = smem_base + row * RSTRIDE + half * 32;

    const int wm = wid & 1, wn = wid >> 1;

    const int la_row = lane & 15;
    const int la_kh  = (lane >> 4) & 1;
    const int lb_n   = (lane & 7) + ((lane & 16) >> 1);
    const int lb_kh  = (lane >> 3) & 1;

    float acc[4][4][4];
#pragma unroll
    for (int i = 0; i < 4; i++)
#pragma unroll
        for (int j = 0; j < 4; j++)
#pragma unroll
            for (int k = 0; k < 4; k++) acc[i][j][k] = 0.f;

#define ISSUE(c, st) do { \
    uint32_t d = sdst + (st) * STAGE; \
    size_t  zo = zbase + (size_t)(c) * 32; \
    size_t  wo = wbase + (size_t)(c) * 32; \
    CP16(d + O_ZH,      (const char*)(g_Zh + zo)); \
    CP16(d + O_ZH + 16, (const char*)(g_Zh + zo + 8)); \
    CP16(d + O_ZL,      (const char*)(g_Zl + zo)); \
    CP16(d + O_ZL + 16, (const char*)(g_Zl + zo + 8)); \
    CP16(d + O_WH,      (const char*)(g_Wh + wo)); \
    CP16(d + O_WH + 16, (const char*)(g_Wh + wo + 8)); \
    CP16(d + O_WL,      (const char*)(g_Wl + wo)); \
    CP16(d + O_WL + 16, (const char*)(g_Wl + wo + 8)); \
} while (0)

    ISSUE(0, 0);
    CP_COMMIT();

    for (int c = 0; c < EDIM / 32; c++) {
        const int st = c & 1;
        if (c + 1 < EDIM / 32) { ISSUE(c + 1, st ^ 1); CP_COMMIT(); CP_WAIT1(); }
        else                   { CP_WAIT0(); }
        __syncthreads();

        const uint32_t sg = smem_base + st * STAGE;
        const uint32_t aZH = sg + O_ZH + (wm * 64 + la_row) * RSTRIDE + la_kh * 16;
        const uint32_t aZL = sg + O_ZL + (wm * 64 + la_row) * RSTRIDE + la_kh * 16;
        const uint32_t bWH = sg + O_WH + (wn * 32 + lb_n) * RSTRIDE + lb_kh * 16;
        const uint32_t bWL = sg + O_WL + (wn * 32 + lb_n) * RSTRIDE + lb_kh * 16;

#pragma unroll
        for (int ks = 0; ks < 2; ks++) {
            const uint32_t ko = ks * 32;
            uint32_t bh[4][2], bl[4][2];
#pragma unroll
            for (int np = 0; np < 2; np++) {
                uint32_t t[4];
                LDSM4(t, bWH + np * 16 * RSTRIDE + ko);
                bh[2*np][0] = t[0]; bh[2*np][1] = t[1];
                bh[2*np+1][0] = t[2]; bh[2*np+1][1] = t[3];
                LDSM4(t, bWL + np * 16 * RSTRIDE + ko);
                bl[2*np][0] = t[0]; bl[2*np][1] = t[1];
                bl[2*np+1][0] = t[2]; bl[2*np+1][1] = t[3];
            }
            // mt-pairs; within a pair, product-major: 8 independent MMAs
            // between successive touches of the same accumulator.
#pragma unroll
            for (int mp = 0; mp < 2; mp++) {
                uint32_t ah[2][4], al[2][4];
                LDSM4(ah[0], aZH + (mp * 2 + 0) * 16 * RSTRIDE + ko);
                LDSM4(ah[1], aZH + (mp * 2 + 1) * 16 * RSTRIDE + ko);
                LDSM4(al[0], aZL + (mp * 2 + 0) * 16 * RSTRIDE + ko);
                LDSM4(al[1], aZL + (mp * 2 + 1) * 16 * RSTRIDE + ko);
#pragma unroll
                for (int m2 = 0; m2 < 2; m2++)
#pragma unroll
                    for (int nt = 0; nt < 4; nt++)
                        MMA_BF16(acc[mp*2+m2][nt], ah[m2], bh[nt]);
#pragma unroll
                for (int m2 = 0; m2 < 2; m2++)
#pragma unroll
                    for (int nt = 0; nt < 4; nt++)
                        MMA_BF16(acc[mp*2+m2][nt], al[m2], bh[nt]);
#pragma unroll
                for (int m2 = 0; m2 < 2; m2++)
#pragma unroll
                    for (int nt = 0; nt < 4; nt++)
                        MMA_BF16(acc[mp*2+m2][nt], ah[m2], bl[nt]);
            }
        }
        __syncthreads();
    }

    const int g = lane >> 2, cq = 2 * (lane & 3);
#pragma unroll
    for (int nt = 0; nt < 4; nt++) {
        const int col = bx * 128 + wn * 32 + nt * 8 + cq;
        const float2 bv = *(const float2*)(bias + col);
#pragma unroll
        for (int mt = 0; mt < 4; mt++) {
            const int r0 = by * 128 + wm * 64 + mt * 16 + g;
            float2 v0 = make_float2(acc[mt][nt][0] + bv.x, acc[mt][nt][1] + bv.y);
            float2 v1 = make_float2(acc[mt][nt][2] + bv.x, acc[mt][nt][3] + bv.y);
            *(float2*)(Y + (size_t)r0 * EDIM + col)       = v0;
            *(float2*)(Y + (size_t)(r0 + 8) * EDIM + col) = v1;
        }
    }
}

// ---------------------------------------------------------------------------
extern "C" void kernel_launch(void* const* d_in, const int* in_sizes, int n_in,
                              void* d_out, int out_size) {
    const float* x     = (const float*)d_in[0];
    const float* theta = (const float*)d_in[1];
    const float* W     = (const float*)d_in[2];
    const float* bias  = (const float*)d_in[3];
    float* out = (float*)d_out;

    cudaFuncSetAttribute(gemm_kernel, cudaFuncAttributeMaxDynamicSharedMemorySize, SMEM_TOTAL);

    qattn_kernel<<<QBLOCKS + EDIM * EDIM / 256, 256>>>(x, theta, W);
    gemm_kernel<<<dim3(EDIM / 128, NTOK / 128), 256, SMEM_TOTAL>>>(bias, out);
}

// round 7
// speedup vs baseline: 1.4562x; 1.2493x over previous
#include <cuda_runtime.h>
#include <cuda_bf16.h>
#include <cuda_fp16.h>
#include <cstdint>

#define NTOK   (8 * 2048)
#define EDIM   512
#define NHEAD  64
#define DK     8

typedef unsigned long long u64;

// Z: single fp16 (|Z|<=1, quant err 2^-11). W: split fp16 (hi + lo).
__device__ __half g_Zf[NTOK * EDIM];
__device__ __half g_Wh[EDIM * EDIM];
__device__ __half g_Wl[EDIM * EDIM];

__device__ __forceinline__ uint32_t smem_to_u32(const void* p) {
    uint32_t a;
    asm("{ .reg .u64 t; cvta.to.shared.u64 t, %1; cvt.u32.u64 %0, t; }" : "=r"(a) : "l"(p));
    return a;
}

// Packed fp32x2 math (Blackwell)
__device__ __forceinline__ void fma2(u64 &d, u64 a, u64 b) {
    asm("fma.rn.f32x2 %0, %1, %2, %3;" : "=l"(d) : "l"(a), "l"(b), "l"(d));
}
__device__ __forceinline__ void add2(u64 &d, u64 a) {
    asm("add.rn.f32x2 %0, %1, %2;" : "=l"(d) : "l"(d), "l"(a));
}
__device__ __forceinline__ u64 pack2(float lo, float hi) {
    u64 r; asm("mov.b64 %0, {%1, %2};" : "=l"(r) : "f"(lo), "f"(hi)); return r;
}
__device__ __forceinline__ float2 unpack2(u64 v) {
    float2 r; asm("mov.b64 {%0, %1}, %2;" : "=f"(r.x), "=f"(r.y) : "l"(v)); return r;
}
__device__ __forceinline__ float ex2(float x) {
    float r; asm("ex2.approx.ftz.f32 %0, %1;" : "=f"(r) : "f"(x)); return r;
}

// Baseline-PTX tensor path (sm_80+)
#define CP16(dst, src) \
    asm volatile("cp.async.cg.shared.global [%0], [%1], 16;" :: "r"(dst), "l"(src))
#define CP_COMMIT()  asm volatile("cp.async.commit_group;" ::: "memory")
#define CP_WAIT1()   asm volatile("cp.async.wait_group 1;" ::: "memory")
#define CP_WAIT0()   asm volatile("cp.async.wait_group 0;" ::: "memory")

#define LDSM4(r, addr) \
    asm volatile("ldmatrix.sync.aligned.m8n8.x4.shared.b16 {%0,%1,%2,%3}, [%4];" \
        : "=r"((r)[0]), "=r"((r)[1]), "=r"((r)[2]), "=r"((r)[3]) : "r"(addr))

#define MMA_F16(d, a, b) \
    asm volatile("mma.sync.aligned.m16n8k16.row.col.f32.f16.f16.f32 " \
        "{%0,%1,%2,%3}, {%4,%5,%6,%7}, {%8,%9}, {%0,%1,%2,%3};" \
        : "+f"((d)[0]), "+f"((d)[1]), "+f"((d)[2]), "+f"((d)[3]) \
        : "r"((a)[0]), "r"((a)[1]), "r"((a)[2]), "r"((a)[3]), "r"((b)[0]), "r"((b)[1]))

// ---------------------------------------------------------------------------
// Kernel A: blocks [0, QBLOCKS): projection + head-axis attention (warp/token)
//           blocks [QBLOCKS, ...): W hi/lo fp16 split (merged launch)
// ---------------------------------------------------------------------------
#define QBLOCKS (NTOK / 8)

__global__ __launch_bounds__(256) void qattn_kernel(const float* __restrict__ x,
                                                    const float* __restrict__ theta,
                                                    const float* __restrict__ W) {
    const int tid = threadIdx.x;

    if (blockIdx.x >= QBLOCKS) {   // -------- W split branch --------
        int i = (blockIdx.x - QBLOCKS) * 256 + tid;
        float w = W[i];
        __half h = __float2half_rn(w);
        g_Wh[i] = h;
        g_Wl[i] = __float2half_rn(w - __half2float(h));
        return;
    }

    __shared__ float Psm[8][NHEAD][DK];
    __shared__ float th[DK];
    if (tid < DK) th[tid] = theta[tid];
    __syncthreads();

    const int w = tid >> 5, lane = tid & 31;
    const int token = blockIdx.x * 8 + w;
    const float* xr = x + (size_t)token * EDIM;

    float pa[8], pb[8];
    {
        float4 v0 = *(const float4*)(xr + lane * 8);
        float4 v1 = *(const float4*)(xr + lane * 8 + 4);
        pa[0] = __cosf(v0.x + th[0]); pa[1] = __cosf(v0.y + th[1]);
        pa[2] = __cosf(v0.z + th[2]); pa[3] = __cosf(v0.w + th[3]);
        pa[4] = __cosf(v1.x + th[4]); pa[5] = __cosf(v1.y + th[5]);
        pa[6] = __cosf(v1.z + th[6]); pa[7] = __cosf(v1.w + th[7]);
        float4 u0 = *(const float4*)(xr + (lane + 32) * 8);
        float4 u1 = *(const float4*)(xr + (lane + 32) * 8 + 4);
        pb[0] = __cosf(u0.x + th[0]); pb[1] = __cosf(u0.y + th[1]);
        pb[2] = __cosf(u0.z + th[2]); pb[3] = __cosf(u0.w + th[3]);
        pb[4] = __cosf(u1.x + th[4]); pb[5] = __cosf(u1.y + th[5]);
        pb[6] = __cosf(u1.z + th[6]); pb[7] = __cosf(u1.w + th[7]);
    }

    float* Pw = &Psm[w][0][0];
    *(float4*)(Pw + lane * 8)            = make_float4(pa[0], pa[1], pa[2], pa[3]);
    *(float4*)(Pw + lane * 8 + 4)        = make_float4(pa[4], pa[5], pa[6], pa[7]);
    *(float4*)(Pw + (lane + 32) * 8)     = make_float4(pb[0], pb[1], pb[2], pb[3]);
    *(float4*)(Pw + (lane + 32) * 8 + 4) = make_float4(pb[4], pb[5], pb[6], pb[7]);
    __syncwarp();

    const float inv = 0.35355339059327373f * 1.4426950408889634f;  // /sqrt(8)/ln2
    u64 uqa[4], uqb[4];
#pragma unroll
    for (int i = 0; i < 4; i++) {
        uqa[i] = pack2(pa[2*i] * inv, pa[2*i+1] * inv);
        uqb[i] = pack2(pb[2*i] * inv, pb[2*i+1] * inv);
    }

    u64 sum2 = 0ull, uoa[4], uob[4];
#pragma unroll
    for (int i = 0; i < 4; i++) { uoa[i] = 0ull; uob[i] = 0ull; }

    const ulonglong2* Pw2 = (const ulonglong2*)Pw;
#pragma unroll 8
    for (int g = 0; g < NHEAD; g++) {
        ulonglong2 p0 = Pw2[g * 2];
        ulonglong2 p1 = Pw2[g * 2 + 1];
        u64 ta = 0ull, tb = 0ull;
        fma2(ta, uqa[0], p0.x); fma2(ta, uqa[1], p0.y);
        fma2(ta, uqa[2], p1.x); fma2(ta, uqa[3], p1.y);
        fma2(tb, uqb[0], p0.x); fma2(tb, uqb[1], p0.y);
        fma2(tb, uqb[2], p1.x); fma2(tb, uqb[3], p1.y);
        float2 va = unpack2(ta), vb = unpack2(tb);
        float wa = ex2(va.x + va.y);
        float wb = ex2(vb.x + vb.y);
        add2(sum2, pack2(wa, wb));
        u64 waa = pack2(wa, wa), wbb = pack2(wb, wb);
        fma2(uoa[0], p0.x, waa); fma2(uoa[1], p0.y, waa);
        fma2(uoa[2], p1.x, waa); fma2(uoa[3], p1.y, waa);
        fma2(uob[0], p0.x, wbb); fma2(uob[1], p0.y, wbb);
        fma2(uob[2], p1.x, wbb); fma2(uob[3], p1.y, wbb);
    }

    float2 sums = unpack2(sum2);
    const float ra = 1.0f / sums.x, rb = 1.0f / sums.y;
    const int b = token >> 11, s = token & 2047;
    const size_t idxA = ((size_t)b << 20) + ((size_t)lane << 14) + s * 8;
    const size_t idxB = ((size_t)b << 20) + ((size_t)(lane + 32) << 14) + s * 8;

    union { __half e[8]; uint4 v; } uf;
#pragma unroll
    for (int i = 0; i < 4; i++) {
        float2 v = unpack2(uoa[i]);
        uf.e[2*i]   = __float2half_rn(v.x * ra);
        uf.e[2*i+1] = __float2half_rn(v.y * ra);
    }
    *(uint4*)(g_Zf + idxA) = uf.v;
#pragma unroll
    for (int i = 0; i < 4; i++) {
        float2 v = unpack2(uob[i]);
        uf.e[2*i]   = __float2half_rn(v.x * rb);
        uf.e[2*i+1] = __float2half_rn(v.y * rb);
    }
    *(uint4*)(g_Zf + idxB) = uf.v;
}

// ---------------------------------------------------------------------------
// Kernel B: HMMA GEMM  Y[16384,512] = Z @ W^T + bias
// fp16 2-product: acc = Z*Wh + Z*Wl  (fp32 accumulate).
// CTA 128x128, 8 warps x (64x32), K chunks of 32, double-buffered cp.async.
// 3 operand arrays (Z, Wh, Wl), row stride 80B -> conflict-free ldmatrix.
// ---------------------------------------------------------------------------
#define RSTRIDE 80
#define ARR     (128 * RSTRIDE)     // 10240 B
#define O_Z     0
#define O_WH    (1 * ARR)
#define O_WL    (2 * ARR)
#define STAGE   (3 * ARR)           // 30720 B
#define SMEM_TOTAL (2 * STAGE)      // 61440 B

__global__ __launch_bounds__(256, 2) void gemm_kernel(const float* __restrict__ bias,
                                                      float* __restrict__ Y) {
    extern __shared__ char smem[];
    const uint32_t smem_base = smem_to_u32(smem);
    const int tid = threadIdx.x, wid = tid >> 5, lane = tid & 31;
    const int bx = blockIdx.x, by = blockIdx.y;

    const int row = tid >> 1, half = tid & 1;
    const size_t zbase = (size_t)(by * 128 + row) * EDIM + half * 16;
    const size_t wbase = (size_t)(bx * 128 + row) * EDIM + half * 16;
    const uint32_t sdst = smem_base + row * RSTRIDE + half * 32;

    const int wm = wid & 1, wn = wid >> 1;

    const int la_row = lane & 15;
    const int la_kh  = (lane >> 4) & 1;
    const int lb_n   = (lane & 7) + ((lane & 16) >> 1);
    const int lb_kh  = (lane >> 3) & 1;

    float acc[4][4][4];
#pragma unroll
    for (int i = 0; i < 4; i++)
#pragma unroll
        for (int j = 0; j < 4; j++)
#pragma unroll
            for (int k = 0; k < 4; k++) acc[i][j][k] = 0.f;

#define ISSUE(c, st) do { \
    uint32_t d = sdst + (st) * STAGE; \
    size_t  zo = zbase + (size_t)(c) * 32; \
    size_t  wo = wbase + (size_t)(c) * 32; \
    CP16(d + O_Z,       (const char*)(g_Zf + zo)); \
    CP16(d + O_Z  + 16, (const char*)(g_Zf + zo + 8)); \
    CP16(d + O_WH,      (const char*)(g_Wh + wo)); \
    CP16(d + O_WH + 16, (const char*)(g_Wh + wo + 8)); \
    CP16(d + O_WL,      (const char*)(g_Wl + wo)); \
    CP16(d + O_WL + 16, (const char*)(g_Wl + wo + 8)); \
} while (0)

    ISSUE(0, 0);
    CP_COMMIT();

    for (int c = 0; c < EDIM / 32; c++) {
        const int st = c & 1;
        if (c + 1 < EDIM / 32) { ISSUE(c + 1, st ^ 1); CP_COMMIT(); CP_WAIT1(); }
        else                   { CP_WAIT0(); }
        __syncthreads();

        const uint32_t sg = smem_base + st * STAGE;
        const uint32_t aZ  = sg + O_Z  + (wm * 64 + la_row) * RSTRIDE + la_kh * 16;
        const uint32_t bWH = sg + O_WH + (wn * 32 + lb_n) * RSTRIDE + lb_kh * 16;
        const uint32_t bWL = sg + O_WL + (wn * 32 + lb_n) * RSTRIDE + lb_kh * 16;

#pragma unroll
        for (int ks = 0; ks < 2; ks++) {
            const uint32_t ko = ks * 32;
            uint32_t bh[4][2], bl[4][2];
#pragma unroll
            for (int np = 0; np < 2; np++) {
                uint32_t t[4];
                LDSM4(t, bWH + np * 16 * RSTRIDE + ko);
                bh[2*np][0] = t[0]; bh[2*np][1] = t[1];
                bh[2*np+1][0] = t[2]; bh[2*np+1][1] = t[3];
                LDSM4(t, bWL + np * 16 * RSTRIDE + ko);
                bl[2*np][0] = t[0]; bl[2*np][1] = t[1];
                bl[2*np+1][0] = t[2]; bl[2*np+1][1] = t[3];
            }
            // mt-pairs; product-major within a pair: 8 independent MMAs
            // between successive touches of the same accumulator.
#pragma unroll
            for (int mp = 0; mp < 2; mp++) {
                uint32_t az[2][4];
                LDSM4(az[0], aZ + (mp * 2 + 0) * 16 * RSTRIDE + ko);
                LDSM4(az[1], aZ + (mp * 2 + 1) * 16 * RSTRIDE + ko);
#pragma unroll
                for (int m2 = 0; m2 < 2; m2++)
#pragma unroll
                    for (int nt = 0; nt < 4; nt++)
                        MMA_F16(acc[mp*2+m2][nt], az[m2], bh[nt]);
#pragma unroll
                for (int m2 = 0; m2 < 2; m2++)
#pragma unroll
                    for (int nt = 0; nt < 4; nt++)
                        MMA_F16(acc[mp*2+m2][nt], az[m2], bl[nt]);
            }
        }
        __syncthreads();
    }

    const int g = lane >> 2, cq = 2 * (lane & 3);
#pragma unroll
    for (int nt = 0; nt < 4; nt++) {
        const int col = bx * 128 + wn * 32 + nt * 8 + cq;
        const float2 bv = *(const float2*)(bias + col);
#pragma unroll
        for (int mt = 0; mt < 4; mt++) {
            const int r0 = by * 128 + wm * 64 + mt * 16 + g;
            float2 v0 = make_float2(acc[mt][nt][0] + bv.x, acc[mt][nt][1] + bv.y);
            float2 v1 = make_float2(acc[mt][nt][2] + bv.x, acc[mt][nt][3] + bv.y);
            *(float2*)(Y + (size_t)r0 * EDIM + col)       = v0;
            *(float2*)(Y + (size_t)(r0 + 8) * EDIM + col) = v1;
        }
    }
}

// ---------------------------------------------------------------------------
extern "C" void kernel_launch(void* const* d_in, const int* in_sizes, int n_in,
                              void* d_out, int out_size) {
    const float* x     = (const float*)d_in[0];
    const float* theta = (const float*)d_in[1];
    const float* W     = (const float*)d_in[2];
    const float* bias  = (const float*)d_in[3];
    float* out = (float*)d_out;

    cudaFuncSetAttribute(gemm_kernel, cudaFuncAttributeMaxDynamicSharedMemorySize, SMEM_TOTAL);

    qattn_kernel<<<QBLOCKS + EDIM * EDIM / 256, 256>>>(x, theta, W);
    gemm_kernel<<<dim3(EDIM / 128, NTOK / 128), 256, SMEM_TOTAL>>>(bias, out);
}